// round 14
// baseline (speedup 1.0000x reference)
#include <cuda_runtime.h>

// Problem constants
#define B_      64
#define S_      512
#define EMB_    300
#define T_      16
#define K4_     75          // EMB_/4
#define C_      32          // chunks per batch
#define CS_     16          // steps per chunk
#define FULL_   0xffffffffu
#define LN16_   2.7725887222397811f

// Packed f32x2 helpers
#define FMA2(d, a, b, c) asm("fma.rn.f32x2 %0, %1, %2, %3;" : "=l"(d) : "l"(a), "l"(b), "l"(c))
#define MUL2b(d, a, b)   asm("mul.rn.f32x2 %0, %1, %2;"     : "=l"(d) : "l"(a), "l"(b))
#define ADD2(d, a, b)    asm("add.rn.f32x2 %0, %1, %2;"     : "=l"(d) : "l"(a), "l"(b))
#define PACK2(d, lo, hi) asm("mov.b64 %0, {%1, %2};"        : "=l"(d) : "f"(lo), "f"(hi))

__device__ __forceinline__ float2 unpack2(unsigned long long v) {
    float2 f;
    asm("mov.b64 {%0, %1}, %2;" : "=f"(f.x), "=f"(f.y) : "l"(v));
    return f;
}

// W and bias in constant memory: warp-uniform reads go through the
// constant/uniform port, NOT the LSU crossbar.  cW2[i] = (W[2i], W[2i+1])
// bit-identical pair; float pair (d, j0=2p..) lives at index d*8 + j/2.
__constant__ double cW2[2400];
__constant__ double cB2[8];

// Scratch: per-(batch,chunk) transfer matrices, transposed:
// g_M[m*256 + j*16 + i] = M_m[i][j]
__device__ float g_M[B_ * C_ * 256];

// ---------------------------------------------------------------------------
// Kernel 1: probs = embed[text] @ W + b.
// 128 threads / 64 tokens per block.  thread = (jh = tid>>6, tok = tid&63):
// each thread produces 8 outputs (j = jh*8..jh*8+7) for its token.
// K staged into SMEM in 2 phases (float4 cols [0,38) then [38,75)), row
// stride 39 (odd) -> e-LDS.128 is conflict-free 128-distinct-byte reads.
// W pairs come from __constant__ (warp-uniform -> LDC/LDCU, off the LSU).
// ---------------------------------------------------------------------------
__global__ void __launch_bounds__(128) probs_kernel(const int*   __restrict__ text,
                                                    const float* __restrict__ embed,
                                                    float*       __restrict__ probs) {
    __shared__ float4 esh[64 * 39];
    __shared__ int    tsh[64];

    int tid = threadIdx.x;
    int tb  = blockIdx.x * 64;

    if (tid < 64) tsh[tid] = text[tb + tid];
    __syncthreads();

    int tok = tid & 63;
    int jh  = tid >> 6;          // 0 or 1; uniform within each warp
    int r   = tid >> 1;          // staging row
    int h   = tid & 1;           // staging half

    unsigned long long acc0 = 0ull, acc1 = 0ull, acc2 = 0ull, acc3 = 0ull;

    #pragma unroll
    for (int ph = 0; ph < 2; ph++) {
        int kb    = ph ? 38 : 0;
        int ncols = ph ? 37 : 38;

        // stage: 2 threads per row, 19 float4 each, coalesced along K
        {
            const float4* src = (const float4*)(embed + (size_t)tsh[r] * EMB_) + kb;
            float4*       dst = esh + r * 39;
            int c0 = h * 19;
            #pragma unroll
            for (int q = 0; q < 19; q++) {
                int c = c0 + q;
                if (c < ncols) dst[c] = src[c];
            }
        }
        __syncthreads();

        const float4* myrow = esh + tok * 39;
        #pragma unroll 2
        for (int k = kb; k < kb + 37; k++) {
            float4 ev = myrow[k - kb];
            unsigned long long e00, e11, e22, e33;
            PACK2(e00, ev.x, ev.x);
            PACK2(e11, ev.y, ev.y);
            PACK2(e22, ev.z, ev.z);
            PACK2(e33, ev.w, ev.w);
            const double* wp = cW2 + 32 * k + jh * 4;
            #pragma unroll
            for (int dd = 0; dd < 4; dd++) {
                unsigned long long e = dd == 0 ? e00 : dd == 1 ? e11 : dd == 2 ? e22 : e33;
                unsigned long long w0 = __double_as_longlong(wp[dd * 8 + 0]);
                unsigned long long w1 = __double_as_longlong(wp[dd * 8 + 1]);
                unsigned long long w2 = __double_as_longlong(wp[dd * 8 + 2]);
                unsigned long long w3 = __double_as_longlong(wp[dd * 8 + 3]);
                FMA2(acc0, e, w0, acc0);
                FMA2(acc1, e, w1, acc1);
                FMA2(acc2, e, w2, acc2);
                FMA2(acc3, e, w3, acc3);
            }
        }
        // phase 0 has 38 cols: do k=37 separately (keeps loop counts equal)
        if (ph == 0) {
            float4 ev = myrow[37];
            unsigned long long e00, e11, e22, e33;
            PACK2(e00, ev.x, ev.x);
            PACK2(e11, ev.y, ev.y);
            PACK2(e22, ev.z, ev.z);
            PACK2(e33, ev.w, ev.w);
            const double* wp = cW2 + 32 * 37 + jh * 4;
            #pragma unroll
            for (int dd = 0; dd < 4; dd++) {
                unsigned long long e = dd == 0 ? e00 : dd == 1 ? e11 : dd == 2 ? e22 : e33;
                FMA2(acc0, e, __double_as_longlong(wp[dd * 8 + 0]), acc0);
                FMA2(acc1, e, __double_as_longlong(wp[dd * 8 + 1]), acc1);
                FMA2(acc2, e, __double_as_longlong(wp[dd * 8 + 2]), acc2);
                FMA2(acc3, e, __double_as_longlong(wp[dd * 8 + 3]), acc3);
            }
        }
        __syncthreads();    // tile consumed; safe to restage
    }

    // bias + store 8 consecutive floats (2 x STG.128)
    ADD2(acc0, acc0, __double_as_longlong(cB2[jh * 4 + 0]));
    ADD2(acc1, acc1, __double_as_longlong(cB2[jh * 4 + 1]));
    ADD2(acc2, acc2, __double_as_longlong(cB2[jh * 4 + 2]));
    ADD2(acc3, acc3, __double_as_longlong(cB2[jh * 4 + 3]));
    float2 f0 = unpack2(acc0), f1 = unpack2(acc1);
    float2 f2 = unpack2(acc2), f3 = unpack2(acc3);
    float4* outp = (float4*)(probs + (size_t)(tb + tok) * T_ + jh * 8);
    outp[0] = make_float4(f0.x, f0.y, f1.x, f1.y);
    outp[1] = make_float4(f2.x, f2.y, f3.x, f3.y);
}

// ---------------------------------------------------------------------------
// Kernel 2: per-(batch,chunk) transfer-matrix products.
// grid 256 x 128: 8 matrices per block (half-warp per matrix).
// ---------------------------------------------------------------------------
__global__ void __launch_bounds__(128) chunk_kernel(const int*   __restrict__ text,
                                                    const float* __restrict__ probs,
                                                    const float* __restrict__ trans) {
    __shared__ float Esh[256];       // Esh[j*16+k] = exp(trans[k][j])
    __shared__ float psh[4][512];

    int tid = threadIdx.x;
    for (int idx = tid; idx < 256; idx += 128) {
        int k = idx >> 4, jj = idx & 15;
        Esh[jj * 16 + k] = __expf(trans[idx]);
    }

    int warp = tid >> 5, lane = tid & 31;
    int half = lane >> 4, li = lane & 15;
    int m = blockIdx.x * 8 + warp * 2 + half;
    int b = m >> 5, c = m & (C_ - 1);

    // len for batch b
    const int4* tx4 = (const int4*)(text + b * S_);
    int cnt = 0;
    #pragma unroll
    for (int q = 0; q < 8; q++) {
        int4 v = tx4[li + q * 16];
        cnt += (v.x != 0) + (v.y != 0) + (v.z != 0) + (v.w != 0);
    }
    #pragma unroll
    for (int o = 8; o; o >>= 1) cnt += __shfl_xor_sync(FULL_, cnt, o);
    int len = cnt;

    // Stage exp(emit)/16 for this chunk's 16 steps
    {
        const float4* p4 = (const float4*)(probs + ((size_t)b * S_ + c * CS_) * T_);
        float* myp = &psh[warp][half * 256];
        #pragma unroll
        for (int q = 0; q < 4; q++) {
            float4 v = p4[li + q * 16];
            int o4 = (li + q * 16) * 4;
            myp[o4 + 0] = __expf(v.x) * 0.0625f;
            myp[o4 + 1] = __expf(v.y) * 0.0625f;
            myp[o4 + 2] = __expf(v.z) * 0.0625f;
            myp[o4 + 3] = __expf(v.w) * 0.0625f;
        }
    }
    __syncthreads();

    float M[16];
    #pragma unroll
    for (int jj = 0; jj < 16; jj++) M[jj] = (jj == li) ? 1.f : 0.f;

    const float* myp = &psh[warp][half * 256];
    #pragma unroll 1
    for (int dt = 0; dt < CS_; dt++) {
        int t = c * CS_ + dt;
        if (t >= 1 && t < len) {
            const float4* pv = (const float4*)(myp + dt * 16);
            float4 pa = pv[0], pb = pv[1], pc = pv[2], pd = pv[3];
            float p[16] = {pa.x, pa.y, pa.z, pa.w,  pb.x, pb.y, pb.z, pb.w,
                           pc.x, pc.y, pc.z, pc.w,  pd.x, pd.y, pd.z, pd.w};
            unsigned long long mp[8];
            #pragma unroll
            for (int q = 0; q < 8; q++) PACK2(mp[q], M[2 * q], M[2 * q + 1]);
            float N[16];
            #pragma unroll
            for (int jj = 0; jj < 16; jj++) {
                const ulonglong2* e2 = (const ulonglong2*)(Esh + jj * 16);
                ulonglong2 ea = e2[0], eb = e2[1], ec = e2[2], ed = e2[3];
                unsigned long long a0, a1;
                MUL2b(a0, mp[0], ea.x);
                FMA2(a0, mp[1], ea.y, a0);
                FMA2(a0, mp[2], eb.x, a0);
                FMA2(a0, mp[3], eb.y, a0);
                MUL2b(a1, mp[4], ec.x);
                FMA2(a1, mp[5], ec.y, a1);
                FMA2(a1, mp[6], ed.x, a1);
                FMA2(a1, mp[7], ed.y, a1);
                ADD2(a0, a0, a1);
                float2 f = unpack2(a0);
                N[jj] = (f.x + f.y) * p[jj];
            }
            #pragma unroll
            for (int jj = 0; jj < 16; jj++) M[jj] = N[jj];
        }
    }

    float* out = g_M + (size_t)m * 256 + li;
    #pragma unroll
    for (int jj = 0; jj < 16; jj++) out[jj * 16] = M[jj];
}

// ---------------------------------------------------------------------------
// Kernel 3: combine + scores.  256 threads per batch row.
// Warp 0: serial combine over 32 chunk matrices (prefetched from L2).
// Warps 1-7: unary+binary scores in parallel.  Lens via ballot.
// ---------------------------------------------------------------------------
__global__ void __launch_bounds__(256) combine_kernel(const int*   __restrict__ text,
                                                      const int*   __restrict__ tags,
                                                      const float* __restrict__ probs,
                                                      const float* __restrict__ trans,
                                                      float*       __restrict__ out_lens,
                                                      float*       __restrict__ out_ll) {
    __shared__ float sA[16];
    __shared__ float scp[8];
    __shared__ int   cnt[8];

    int tid  = threadIdx.x;
    int warp = tid >> 5, lane = tid & 31;
    int b    = blockIdx.x;

    // lens via ballot: thread covers s = tid and s = tid + 256
    {
        unsigned b0 = __ballot_sync(FULL_, text[b * S_ + tid] != 0);
        unsigned b1 = __ballot_sync(FULL_, text[b * S_ + tid + 256] != 0);
        if (lane == 0) cnt[warp] = __popc(b0) + __popc(b1);
    }
    __syncthreads();
    int len = 0;
    #pragma unroll
    for (int q = 0; q < 8; q++) len += cnt[q];

    const float* pb = probs + (size_t)b * S_ * T_;

    if (warp == 0) {
        int j = lane & 15;
        float a[16];
        {
            const float4* p4 = (const float4*)pb;
            #pragma unroll
            for (int q = 0; q < 4; q++) {
                float4 v = p4[q];
                a[4*q+0] = v.x; a[4*q+1] = v.y; a[4*q+2] = v.z; a[4*q+3] = v.w;
            }
        }
        float mx = a[0];
        #pragma unroll
        for (int i = 1; i < 16; i++) mx = fmaxf(mx, a[i]);
        float L = mx;
        #pragma unroll
        for (int i = 0; i < 16; i++) a[i] = __expf(a[i] - mx);

        const ulonglong2* MT = (const ulonglong2*)(g_M + (size_t)b * C_ * 256);
        ulonglong2 mc[4];
        #pragma unroll
        for (int q = 0; q < 4; q++) mc[q] = MT[j * 4 + q];

        #pragma unroll 1
        for (int c = 0; c < C_; c++) {
            ulonglong2 mn[4];
            if (c + 1 < C_) {
                #pragma unroll
                for (int q = 0; q < 4; q++) mn[q] = MT[(c + 1) * 64 + j * 4 + q];
            }
            int t0 = (c == 0) ? 1 : c * CS_;
            int hi = c * CS_ + CS_ - 1;
            int te = (len - 1 < hi) ? len - 1 : hi;
            int n  = te - t0 + 1;
            if (n > 0) {
                unsigned long long ap[8];
                #pragma unroll
                for (int q = 0; q < 8; q++) PACK2(ap[q], a[2*q], a[2*q+1]);
                unsigned long long a0, a1;
                MUL2b(a0, ap[0], mc[0].x);
                FMA2(a0, ap[1], mc[0].y, a0);
                FMA2(a0, ap[2], mc[1].x, a0);
                FMA2(a0, ap[3], mc[1].y, a0);
                MUL2b(a1, ap[4], mc[2].x);
                FMA2(a1, ap[5], mc[2].y, a1);
                FMA2(a1, ap[6], mc[3].x, a1);
                FMA2(a1, ap[7], mc[3].y, a1);
                ADD2(a0, a0, a1);
                float2 f = unpack2(a0);
                if (lane < 16) sA[j] = f.x + f.y;
                __syncwarp();
                {
                    const float4* s4 = (const float4*)sA;
                    #pragma unroll
                    for (int q = 0; q < 4; q++) {
                        float4 v = s4[q];
                        a[4*q+0] = v.x; a[4*q+1] = v.y;
                        a[4*q+2] = v.z; a[4*q+3] = v.w;
                    }
                }
                __syncwarp();
                float mm = a[0];
                #pragma unroll
                for (int i = 1; i < 16; i++) mm = fmaxf(mm, a[i]);
                float r = __frcp_rn(mm);
                #pragma unroll
                for (int i = 0; i < 16; i++) a[i] *= r;
                L += __logf(mm) + (float)n * LN16_;
            }
            #pragma unroll
            for (int q = 0; q < 4; q++) mc[q] = mn[q];
        }
        float ssum = 0.f;
        #pragma unroll
        for (int i = 0; i < 16; i++) ssum += a[i];
        if (lane == 0) scp[0] = -(L + __logf(ssum));
    } else {
        // scores: t = tid-32 in 0..223 covers s = t, t+224, (t<64: t+448)
        const int* tg = tags + b * S_;
        float sc = 0.f;
        int t = tid - 32;
        {
            int s = t;
            if (s < len) {
                int tg1 = tg[s];
                sc += pb[s * T_ + tg1];
                if (s >= 1) sc += trans[tg[s - 1] * T_ + tg1];
            }
        }
        {
            int s = t + 224;
            if (s < len) {
                int tg1 = tg[s];
                sc += pb[s * T_ + tg1];
                sc += trans[tg[s - 1] * T_ + tg1];
            }
        }
        if (t < 64) {
            int s = t + 448;
            if (s < len) {
                int tg1 = tg[s];
                sc += pb[s * T_ + tg1];
                sc += trans[tg[s - 1] * T_ + tg1];
            }
        }
        #pragma unroll
        for (int o = 16; o; o >>= 1) sc += __shfl_xor_sync(FULL_, sc, o);
        if (lane == 0) scp[warp] = sc;
    }
    __syncthreads();

    if (tid == 0) {
        float tot = 0.f;
        #pragma unroll
        for (int q = 0; q < 8; q++) tot += scp[q];
        out_ll[b]   = tot;
        out_lens[b] = (float)len;
    }
}

// ---------------------------------------------------------------------------
// Launch.  Output layout: probs [0,524288) | lens [524288,524352) | ll [...)
// ---------------------------------------------------------------------------
extern "C" void kernel_launch(void* const* d_in, const int* in_sizes, int n_in,
                              void* d_out, int out_size) {
    const int*   text  = (const int*)  d_in[0];
    const int*   tags  = (const int*)  d_in[1];
    const float* embed = (const float*)d_in[2];
    const float* W     = (const float*)d_in[3];
    const float* bias  = (const float*)d_in[4];
    const float* trans = (const float*)d_in[5];

    float* out      = (float*)d_out;
    float* probs    = out;
    float* out_lens = out + B_ * S_ * T_;
    float* out_ll   = out_lens + B_;

    // W and bias into constant memory (device-to-device, graph-capturable)
    cudaMemcpyToSymbolAsync(cW2, W,    EMB_ * T_ * sizeof(float), 0,
                            cudaMemcpyDeviceToDevice, 0);
    cudaMemcpyToSymbolAsync(cB2, bias, T_ * sizeof(float), 0,
                            cudaMemcpyDeviceToDevice, 0);

    probs_kernel  <<<(B_ * S_) / 64, 128>>>(text, embed, probs);
    chunk_kernel  <<<(B_ * C_) / 8, 128>>>(text, probs, trans);
    combine_kernel<<<B_, 256>>>(text, tags, probs, trans, out_lens, out_ll);
}

// round 15
// speedup vs baseline: 1.9886x; 1.9886x over previous
#include <cuda_runtime.h>
#include <cuda_bf16.h>

// Problem constants
#define B_      64
#define S_      512
#define EMB_    300
#define T_      16
#define C_      32          // chunks per batch
#define CS_     16          // steps per chunk
#define FULL_   0xffffffffu
#define LN16_   2.7725887222397811f

// Packed f32x2 helpers (CRF kernels)
#define FMA2(d, a, b, c) asm("fma.rn.f32x2 %0, %1, %2, %3;" : "=l"(d) : "l"(a), "l"(b), "l"(c))
#define MUL2b(d, a, b)   asm("mul.rn.f32x2 %0, %1, %2;"     : "=l"(d) : "l"(a), "l"(b))
#define ADD2(d, a, b)    asm("add.rn.f32x2 %0, %1, %2;"     : "=l"(d) : "l"(a), "l"(b))
#define PACK2(d, lo, hi) asm("mov.b64 %0, {%1, %2};"        : "=l"(d) : "f"(lo), "f"(hi))

__device__ __forceinline__ float2 unpack2(unsigned long long v) {
    float2 f;
    asm("mov.b64 {%0, %1}, %2;" : "=f"(f.x), "=f"(f.y) : "l"(v));
    return f;
}

// Scratch: per-(batch,chunk) transfer matrices, transposed
__device__ float g_M[B_ * C_ * 256];

// ---------------------------------------------------------------------------
// Tensor-core helpers
// ---------------------------------------------------------------------------
__device__ __forceinline__ unsigned smem_u32(const void* p) {
    unsigned a;
    asm("{ .reg .u64 t; cvta.to.shared.u64 t, %1; cvt.u32.u64 %0, t; }"
        : "=r"(a) : "l"(p));
    return a;
}

__device__ __forceinline__ void mma_bf16(float* d,
                                         unsigned a0, unsigned a1, unsigned a2, unsigned a3,
                                         unsigned b0, unsigned b1) {
    asm volatile("mma.sync.aligned.m16n8k16.row.col.f32.bf16.bf16.f32 "
                 "{%0,%1,%2,%3}, {%4,%5,%6,%7}, {%8,%9}, {%0,%1,%2,%3};"
                 : "+f"(d[0]), "+f"(d[1]), "+f"(d[2]), "+f"(d[3])
                 : "r"(a0), "r"(a1), "r"(a2), "r"(a3), "r"(b0), "r"(b1));
}

__device__ __forceinline__ void ldsm_x4_trans(unsigned& r0, unsigned& r1,
                                              unsigned& r2, unsigned& r3, unsigned addr) {
    asm volatile("ldmatrix.sync.aligned.m8n8.x4.trans.shared.b16 {%0,%1,%2,%3}, [%4];"
                 : "=r"(r0), "=r"(r1), "=r"(r2), "=r"(r3) : "r"(addr));
}

// Exact split: v = hi + residual (residual exactly representable), lo = bf16(residual)
__device__ __forceinline__ void split2(float2 v, unsigned& hi, unsigned& lo) {
    asm("cvt.rn.bf16x2.f32 %0, %1, %2;" : "=r"(hi) : "f"(v.y), "f"(v.x));
    float hx = __uint_as_float(hi << 16);
    float hy = __uint_as_float(hi & 0xffff0000u);
    float rx = v.x - hx;
    float ry = v.y - hy;
    asm("cvt.rn.bf16x2.f32 %0, %1, %2;" : "=r"(lo) : "f"(ry), "f"(rx));
}

// ---------------------------------------------------------------------------
// Kernel 1: probs = embed[text] @ W + b via bf16 split-MMA (3 HMMA per tile).
// Block = 128 thr / 4 warps / 64 tokens; warp = one m16 tile x full n16.
// A fragments loaded DIRECTLY from gathered embed rows (LDG.64, all bytes
// useful) and split to bf16 hi/lo in registers.  W pre-split into SMEM
// (stride 24 bf16 = 48B -> conflict-free ldmatrix.x4.trans).
// K padded 300 -> 304 (W pad rows zeroed, A tail predicated).
// ---------------------------------------------------------------------------
__global__ void __launch_bounds__(128) probs_kernel(const int*   __restrict__ text,
                                                    const float* __restrict__ embed,
                                                    const float* __restrict__ W,
                                                    const float* __restrict__ bias,
                                                    float*       __restrict__ probs) {
    __shared__ __nv_bfloat16 Whi[304 * 24];
    __shared__ __nv_bfloat16 Wlo[304 * 24];
    __shared__ int   tsh[64];
    __shared__ float bsh[16];

    int tid = threadIdx.x;
    int tb  = blockIdx.x * 64;

    if (tid < 64) tsh[tid] = text[tb + tid];
    if (tid < 16) bsh[tid] = bias[tid];

    // split W into bf16 hi/lo planes
    for (int idx = tid; idx < EMB_ * T_; idx += 128) {
        int k = idx >> 4, n = idx & 15;
        float w  = W[idx];
        unsigned hb;
        asm("cvt.rn.bf16x2.f32 %0, %1, %2;" : "=r"(hb) : "f"(0.f), "f"(w));
        float hf = __uint_as_float(hb << 16);
        Whi[k * 24 + n] = __ushort_as_bfloat16((unsigned short)(hb & 0xffff));
        Wlo[k * 24 + n] = __float2bfloat16(w - hf);
    }
    if (tid < 64) {   // zero pad rows 300..303
        int k = 300 + (tid >> 4), n = tid & 15;
        Whi[k * 24 + n] = __ushort_as_bfloat16(0);
        Wlo[k * 24 + n] = __ushort_as_bfloat16(0);
    }
    __syncthreads();

    int warp = tid >> 5, lane = tid & 31;
    int qr = lane >> 2;          // 0..7
    int qc = lane & 3;           // 0..3

    const float* base0 = embed + (size_t)tsh[warp * 16 + qr]     * EMB_ + 2 * qc;
    const float* base1 = embed + (size_t)tsh[warp * 16 + qr + 8] * EMB_ + 2 * qc;

    // ldmatrix.x4.trans per-lane row addresses (4 8x8 tiles: k0/n0,k8/n0,k0/n8,k8/n8)
    int mi   = lane >> 3;
    int krow = ((mi & 1) << 3) + (lane & 7);
    int ncol = (mi >> 1) << 3;
    unsigned bhi_addr = smem_u32(&Whi[krow * 24 + ncol]);
    unsigned blo_addr = smem_u32(&Wlo[krow * 24 + ncol]);

    float d0[4] = {0.f, 0.f, 0.f, 0.f};
    float d1[4] = {0.f, 0.f, 0.f, 0.f};

    float2 p0 = *(const float2*)(base0);
    float2 p1 = *(const float2*)(base1);
    float2 p2 = *(const float2*)(base0 + 8);
    float2 p3 = *(const float2*)(base1 + 8);

    #pragma unroll 1
    for (int s = 0; s < 19; s++) {
        float2 n0, n1, n2, n3;
        bool more = (s < 18);
        if (more) {
            int k = 16 * (s + 1);
            n0 = *(const float2*)(base0 + k);
            n1 = *(const float2*)(base1 + k);
            bool v23 = (s < 17) || (qc < 2);   // tail: k 300..303 invalid
            n2 = v23 ? *(const float2*)(base0 + k + 8) : make_float2(0.f, 0.f);
            n3 = v23 ? *(const float2*)(base1 + k + 8) : make_float2(0.f, 0.f);
        }

        unsigned ah0, al0, ah1, al1, ah2, al2, ah3, al3;
        split2(p0, ah0, al0);
        split2(p1, ah1, al1);
        split2(p2, ah2, al2);
        split2(p3, ah3, al3);

        unsigned bh0, bh1, bh2, bh3, bl0, bl1, bl2, bl3;
        ldsm_x4_trans(bh0, bh1, bh2, bh3, bhi_addr + s * 768);   // 16 rows * 48B
        ldsm_x4_trans(bl0, bl1, bl2, bl3, blo_addr + s * 768);

        mma_bf16(d0, ah0, ah1, ah2, ah3, bh0, bh1);
        mma_bf16(d0, ah0, ah1, ah2, ah3, bl0, bl1);
        mma_bf16(d0, al0, al1, al2, al3, bh0, bh1);
        mma_bf16(d1, ah0, ah1, ah2, ah3, bh2, bh3);
        mma_bf16(d1, ah0, ah1, ah2, ah3, bl2, bl3);
        mma_bf16(d1, al0, al1, al2, al3, bh2, bh3);

        if (more) { p0 = n0; p1 = n1; p2 = n2; p3 = n3; }
    }

    int row0 = tb + warp * 16 + qr;
    int row1 = row0 + 8;
    float b00 = bsh[2 * qc],     b01 = bsh[2 * qc + 1];
    float b10 = bsh[8 + 2 * qc], b11 = bsh[8 + 2 * qc + 1];
    *(float2*)(probs + (size_t)row0 * T_ + 2 * qc)     = make_float2(d0[0] + b00, d0[1] + b01);
    *(float2*)(probs + (size_t)row1 * T_ + 2 * qc)     = make_float2(d0[2] + b00, d0[3] + b01);
    *(float2*)(probs + (size_t)row0 * T_ + 8 + 2 * qc) = make_float2(d1[0] + b10, d1[1] + b11);
    *(float2*)(probs + (size_t)row1 * T_ + 8 + 2 * qc) = make_float2(d1[2] + b10, d1[3] + b11);
}

// ---------------------------------------------------------------------------
// Kernel 2: per-(batch,chunk) transfer-matrix products.
// ---------------------------------------------------------------------------
__global__ void __launch_bounds__(128) chunk_kernel(const int*   __restrict__ text,
                                                    const float* __restrict__ probs,
                                                    const float* __restrict__ trans) {
    __shared__ float Esh[256];       // Esh[j*16+k] = exp(trans[k][j])
    __shared__ float psh[4][512];

    int tid = threadIdx.x;
    for (int idx = tid; idx < 256; idx += 128) {
        int k = idx >> 4, jj = idx & 15;
        Esh[jj * 16 + k] = __expf(trans[idx]);
    }

    int warp = tid >> 5, lane = tid & 31;
    int half = lane >> 4, li = lane & 15;
    int m = blockIdx.x * 8 + warp * 2 + half;
    int b = m >> 5, c = m & (C_ - 1);

    const int4* tx4 = (const int4*)(text + b * S_);
    int cnt = 0;
    #pragma unroll
    for (int q = 0; q < 8; q++) {
        int4 v = tx4[li + q * 16];
        cnt += (v.x != 0) + (v.y != 0) + (v.z != 0) + (v.w != 0);
    }
    #pragma unroll
    for (int o = 8; o; o >>= 1) cnt += __shfl_xor_sync(FULL_, cnt, o);
    int len = cnt;

    {
        const float4* p4 = (const float4*)(probs + ((size_t)b * S_ + c * CS_) * T_);
        float* myp = &psh[warp][half * 256];
        #pragma unroll
        for (int q = 0; q < 4; q++) {
            float4 v = p4[li + q * 16];
            int o4 = (li + q * 16) * 4;
            myp[o4 + 0] = __expf(v.x) * 0.0625f;
            myp[o4 + 1] = __expf(v.y) * 0.0625f;
            myp[o4 + 2] = __expf(v.z) * 0.0625f;
            myp[o4 + 3] = __expf(v.w) * 0.0625f;
        }
    }
    __syncthreads();

    float M[16];
    #pragma unroll
    for (int jj = 0; jj < 16; jj++) M[jj] = (jj == li) ? 1.f : 0.f;

    const float* myp = &psh[warp][half * 256];
    #pragma unroll 1
    for (int dt = 0; dt < CS_; dt++) {
        int t = c * CS_ + dt;
        if (t >= 1 && t < len) {
            const float4* pv = (const float4*)(myp + dt * 16);
            float4 pa = pv[0], pb = pv[1], pc = pv[2], pd = pv[3];
            float p[16] = {pa.x, pa.y, pa.z, pa.w,  pb.x, pb.y, pb.z, pb.w,
                           pc.x, pc.y, pc.z, pc.w,  pd.x, pd.y, pd.z, pd.w};
            unsigned long long mp[8];
            #pragma unroll
            for (int q = 0; q < 8; q++) PACK2(mp[q], M[2 * q], M[2 * q + 1]);
            float N[16];
            #pragma unroll
            for (int jj = 0; jj < 16; jj++) {
                const ulonglong2* e2 = (const ulonglong2*)(Esh + jj * 16);
                ulonglong2 ea = e2[0], eb = e2[1], ec = e2[2], ed = e2[3];
                unsigned long long a0, a1;
                MUL2b(a0, mp[0], ea.x);
                FMA2(a0, mp[1], ea.y, a0);
                FMA2(a0, mp[2], eb.x, a0);
                FMA2(a0, mp[3], eb.y, a0);
                MUL2b(a1, mp[4], ec.x);
                FMA2(a1, mp[5], ec.y, a1);
                FMA2(a1, mp[6], ed.x, a1);
                FMA2(a1, mp[7], ed.y, a1);
                ADD2(a0, a0, a1);
                float2 f = unpack2(a0);
                N[jj] = (f.x + f.y) * p[jj];
            }
            #pragma unroll
            for (int jj = 0; jj < 16; jj++) M[jj] = N[jj];
        }
    }

    float* out = g_M + (size_t)m * 256 + li;
    #pragma unroll
    for (int jj = 0; jj < 16; jj++) out[jj * 16] = M[jj];
}

// ---------------------------------------------------------------------------
// Kernel 3: combine + scores.  256 threads per batch row.
// ---------------------------------------------------------------------------
__global__ void __launch_bounds__(256) combine_kernel(const int*   __restrict__ text,
                                                      const int*   __restrict__ tags,
                                                      const float* __restrict__ probs,
                                                      const float* __restrict__ trans,
                                                      float*       __restrict__ out_lens,
                                                      float*       __restrict__ out_ll) {
    __shared__ float sA[16];
    __shared__ float scp[8];
    __shared__ int   cnt[8];

    int tid  = threadIdx.x;
    int warp = tid >> 5, lane = tid & 31;
    int b    = blockIdx.x;

    {
        unsigned b0 = __ballot_sync(FULL_, text[b * S_ + tid] != 0);
        unsigned b1 = __ballot_sync(FULL_, text[b * S_ + tid + 256] != 0);
        if (lane == 0) cnt[warp] = __popc(b0) + __popc(b1);
    }
    __syncthreads();
    int len = 0;
    #pragma unroll
    for (int q = 0; q < 8; q++) len += cnt[q];

    const float* pb = probs + (size_t)b * S_ * T_;

    if (warp == 0) {
        int j = lane & 15;
        float a[16];
        {
            const float4* p4 = (const float4*)pb;
            #pragma unroll
            for (int q = 0; q < 4; q++) {
                float4 v = p4[q];
                a[4*q+0] = v.x; a[4*q+1] = v.y; a[4*q+2] = v.z; a[4*q+3] = v.w;
            }
        }
        float mx = a[0];
        #pragma unroll
        for (int i = 1; i < 16; i++) mx = fmaxf(mx, a[i]);
        float L = mx;
        #pragma unroll
        for (int i = 0; i < 16; i++) a[i] = __expf(a[i] - mx);

        const ulonglong2* MT = (const ulonglong2*)(g_M + (size_t)b * C_ * 256);
        ulonglong2 mc[4];
        #pragma unroll
        for (int q = 0; q < 4; q++) mc[q] = MT[j * 4 + q];

        #pragma unroll 1
        for (int c = 0; c < C_; c++) {
            ulonglong2 mn[4];
            if (c + 1 < C_) {
                #pragma unroll
                for (int q = 0; q < 4; q++) mn[q] = MT[(c + 1) * 64 + j * 4 + q];
            }
            int t0 = (c == 0) ? 1 : c * CS_;
            int hi = c * CS_ + CS_ - 1;
            int te = (len - 1 < hi) ? len - 1 : hi;
            int n  = te - t0 + 1;
            if (n > 0) {
                unsigned long long ap[8];
                #pragma unroll
                for (int q = 0; q < 8; q++) PACK2(ap[q], a[2*q], a[2*q+1]);
                unsigned long long a0, a1;
                MUL2b(a0, ap[0], mc[0].x);
                FMA2(a0, ap[1], mc[0].y, a0);
                FMA2(a0, ap[2], mc[1].x, a0);
                FMA2(a0, ap[3], mc[1].y, a0);
                MUL2b(a1, ap[4], mc[2].x);
                FMA2(a1, ap[5], mc[2].y, a1);
                FMA2(a1, ap[6], mc[3].x, a1);
                FMA2(a1, ap[7], mc[3].y, a1);
                ADD2(a0, a0, a1);
                float2 f = unpack2(a0);
                if (lane < 16) sA[j] = f.x + f.y;
                __syncwarp();
                {
                    const float4* s4 = (const float4*)sA;
                    #pragma unroll
                    for (int q = 0; q < 4; q++) {
                        float4 v = s4[q];
                        a[4*q+0] = v.x; a[4*q+1] = v.y;
                        a[4*q+2] = v.z; a[4*q+3] = v.w;
                    }
                }
                __syncwarp();
                float mm = a[0];
                #pragma unroll
                for (int i = 1; i < 16; i++) mm = fmaxf(mm, a[i]);
                float r = __frcp_rn(mm);
                #pragma unroll
                for (int i = 0; i < 16; i++) a[i] *= r;
                L += __logf(mm) + (float)n * LN16_;
            }
            #pragma unroll
            for (int q = 0; q < 4; q++) mc[q] = mn[q];
        }
        float ssum = 0.f;
        #pragma unroll
        for (int i = 0; i < 16; i++) ssum += a[i];
        if (lane == 0) scp[0] = -(L + __logf(ssum));
    } else {
        const int* tg = tags + b * S_;
        float sc = 0.f;
        int t = tid - 32;
        {
            int s = t;
            if (s < len) {
                int tg1 = tg[s];
                sc += pb[s * T_ + tg1];
                if (s >= 1) sc += trans[tg[s - 1] * T_ + tg1];
            }
        }
        {
            int s = t + 224;
            if (s < len) {
                int tg1 = tg[s];
                sc += pb[s * T_ + tg1];
                sc += trans[tg[s - 1] * T_ + tg1];
            }
        }
        if (t < 64) {
            int s = t + 448;
            if (s < len) {
                int tg1 = tg[s];
                sc += pb[s * T_ + tg1];
                sc += trans[tg[s - 1] * T_ + tg1];
            }
        }
        #pragma unroll
        for (int o = 16; o; o >>= 1) sc += __shfl_xor_sync(FULL_, sc, o);
        if (lane == 0) scp[warp] = sc;
    }
    __syncthreads();

    if (tid == 0) {
        float tot = 0.f;
        #pragma unroll
        for (int q = 0; q < 8; q++) tot += scp[q];
        out_ll[b]   = tot;
        out_lens[b] = (float)len;
    }
}

// ---------------------------------------------------------------------------
// Launch.  Output layout: probs [0,524288) | lens [524288,524352) | ll [...)
// ---------------------------------------------------------------------------
extern "C" void kernel_launch(void* const* d_in, const int* in_sizes, int n_in,
                              void* d_out, int out_size) {
    const int*   text  = (const int*)  d_in[0];
    const int*   tags  = (const int*)  d_in[1];
    const float* embed = (const float*)d_in[2];
    const float* W     = (const float*)d_in[3];
    const float* bias  = (const float*)d_in[4];
    const float* trans = (const float*)d_in[5];

    float* out      = (float*)d_out;
    float* probs    = out;
    float* out_lens = out + B_ * S_ * T_;
    float* out_ll   = out_lens + B_;

    probs_kernel  <<<(B_ * S_) / 64, 128>>>(text, embed, W, bias, probs);
    chunk_kernel  <<<(B_ * C_) / 8, 128>>>(text, probs, trans);
    combine_kernel<<<B_, 256>>>(text, tags, probs, trans, out_lens, out_ll);
}